// round 5
// baseline (speedup 1.0000x reference)
#include <cuda_runtime.h>
#include <math.h>

#define BATCH 8
#define IMH 512
#define IMW 512
#define NP 11
#define FH 128
#define FW 128
#define NMAPS (BATCH * NP)

// packed derived parameters
// [0,539)    sw   : 11 score filters, 7x7 each          (sw[k*49+tap])
// [539,550)  sbias: 11 score biases
// [550,844)  cw   : 3 cascades x 2 dims x 49 taps       (cw[(i*2+j)*49+tap])
// [844,850)  cb   : 3 cascades x 2 dims
#define OFF_SW    0
#define OFF_SBIAS 539
#define OFF_CW    550
#define OFF_CB    844
#define NPARAMS   850

__device__    float g_params_dev[NPARAMS];
__constant__  float c_params[NPARAMS];

__device__ float g_scores[NMAPS * FH * FW];
__device__ unsigned long long g_best[NMAPS];
__device__ unsigned int       g_count[NMAPS];

// ---------------------------------------------------------------------------
// Kernel 1: fold weights — 17 blocks (one per output row of the 17x256
// coefficient matrix [11 fc rows + 6 head rows]), 256 threads each.
// Lanes map to taps -> bw reads are coalesced 50-float runs. 5 channel
// chunks per output, smem partial reduce (fixed order -> deterministic).
// Block 16 also resets the argmax combine state.
// ---------------------------------------------------------------------------
__global__ void prep_kernel(const float* __restrict__ bw,
                            const float* __restrict__ bb,
                            const float* __restrict__ fcw,
                            const float* __restrict__ fcb,
                            const float* __restrict__ hw,
                            const float* __restrict__ hb) {
    __shared__ float part[256];
    const int r = blockIdx.x;                 // 0..16
    const int t = threadIdx.x;                // 0..255

    if (r == 16 && t < NMAPS) { g_best[t] = 0ULL; g_count[t] = 0u; }

    const int ij = r - 11;                    // valid when r >= 11
    float acc = 0.f;
    if (t < 250) {
        const int chunk = t / 50;
        const int p = t - chunk * 50;         // 0..49 (49 = bias slot)
        if (p < 49) {
            for (int c = chunk; c < 256; c += 5) {
                const float* base = bw + c * 147 + p;
                float we = base[0] + base[49] + base[98];
                float coef = (r < 11) ? fcw[r * 256 + c]
                                      : hw[((ij >> 1) * 256 + c) * 2 + (ij & 1)];
                acc += coef * we;
            }
        } else {
            for (int c = chunk; c < 256; c += 5) {
                float coef = (r < 11) ? fcw[r * 256 + c]
                                      : hw[((ij >> 1) * 256 + c) * 2 + (ij & 1)];
                acc += coef * bb[c];
            }
        }
    }
    part[t] = acc;
    __syncthreads();

    if (t < 50) {
        float tot = part[t] + part[t + 50] + part[t + 100] +
                    part[t + 150] + part[t + 200];
        int slot; float base = 0.f;
        if (r < 11) {
            if (t < 49) slot = OFF_SW + r * 49 + t;
            else      { slot = OFF_SBIAS + r; base = fcb[r]; }
        } else {
            if (t < 49) slot = OFF_CW + ij * 49 + t;
            else      { slot = OFF_CB + ij; base = hb[ij]; }
        }
        g_params_dev[slot] = base + tot;
    }
}

// ---------------------------------------------------------------------------
// Kernel 2: 11-channel 7x7 stride-4 pad-3 conv of normalized image -> scores.
// Block = batch x (16 x 32) output tile; input tile in smem; weights from
// __constant__ (uniform across block -> const-bank FFMA operands).
// ---------------------------------------------------------------------------
__global__ void conv_kernel(const float* __restrict__ img) {
    __shared__ float tile[70 * 134];
    const int tx = blockIdx.x;
    const int ty = blockIdx.y;
    const int b  = blockIdx.z;
    const int tid = threadIdx.x;              // 256

    const float* imb = img + (size_t)b * IMH * IMW;
    const int ir0 = ty * 64 - 3;
    const int ic0 = tx * 128 - 3;

    for (int i = tid; i < 70 * 134; i += 256) {
        int r = i / 134, c = i - r * 134;
        int gr = ir0 + r, gc = ic0 + c;
        float v = 0.f;
        if (gr >= 0 && gr < IMH && gc >= 0 && gc < IMW)
            v = imb[gr * IMW + gc] - 0.5f;
        tile[i] = v;
    }
    __syncthreads();

    #pragma unroll
    for (int it = 0; it < 2; ++it) {
        int pos = tid + it * 256;
        int oyl = pos >> 5, oxl = pos & 31;
        float acc[NP];
        #pragma unroll
        for (int k = 0; k < NP; ++k) acc[k] = c_params[OFF_SBIAS + k];
        #pragma unroll
        for (int kh = 0; kh < 7; ++kh) {
            #pragma unroll
            for (int kw = 0; kw < 7; ++kw) {
                float v = tile[(oyl * 4 + kh) * 134 + oxl * 4 + kw];
                #pragma unroll
                for (int k = 0; k < NP; ++k)
                    acc[k] += v * c_params[OFF_SW + k * 49 + kh * 7 + kw];
            }
        }
        int oy = ty * 16 + oyl, ox = tx * 32 + oxl;
        #pragma unroll
        for (int k = 0; k < NP; ++k)
            g_scores[((b * NP + k) * FH + oy) * FW + ox] = acc[k];
    }
}

// ---------------------------------------------------------------------------
// Kernel 3: argmax over bilinear-upsampled field + cascades, split 4 blocks
// per map. Per cell-row group (same y0) the field is linear in wy -> max at
// endpoint rows (first/last output row of the group). Rolling x-interp:
// tC (row g) carried, tD (row g+1) computed; v = tC + w*(tD - tC) with
// w/oy picked by sign of (tD-tC). Per-map combine via atomicMax on
// (sortable value << 32 | ~idx) key (first-occurrence tie-break). Last block
// to finish a map runs the 3 cascade refinements (warp 0).
// ---------------------------------------------------------------------------
__global__ void argmax_cascade_kernel(const float* __restrict__ img,
                                      float* __restrict__ out) {
    __shared__ float  s[33 * 128];             // score rows of this split
    __shared__ float4 tab[128];                // per-group {wl, wh, olo, ohi}
    __shared__ float  rv[512];
    __shared__ int    ri[512];
    __shared__ unsigned int s_ticket;

    const int sp  = blockIdx.x;                // 0..3 (row split)
    const int m   = blockIdx.y;                // 0..87 (map)
    const int tid = threadIdx.x;               // 512
    const float STEP = 127.0f / 511.0f;
    const int g0 = sp * 32;
    const int nrows = (sp < 3) ? 33 : 32;
    const float* smap = g_scores + (size_t)m * FH * FW;

    // load rows [g0, g0+nrows)
    {
        const float4* src = (const float4*)(smap + g0 * 128);
        float4* dst = (float4*)s;
        const int n4 = nrows * 32;
        for (int i = tid; i < n4; i += 512) dst[i] = src[i];
    }
    if (tid < 128) tab[tid].z = -1.0f;
    __syncthreads();

    // build per-group endpoint table (oy stored as int bits in .z/.w)
    {
        const int oy = tid;
        float ys = (float)oy * STEP;
        int y0 = (int)ys;
        float wy = ys - (float)y0;
        int y0m = (oy > 0)   ? (int)((float)(oy - 1) * STEP) : -1;
        int y0p = (oy < 511) ? (int)((float)(oy + 1) * STEP) : 128;
        if (y0m != y0) { tab[y0].x = wy; tab[y0].z = __int_as_float(oy); }
        if (y0p != y0) { tab[y0].y = wy; tab[y0].w = __int_as_float(oy); }
    }
    __syncthreads();

    // column scan
    const int ox = tid;
    float xs = (float)ox * STEP;
    int x0 = (int)xs;
    int x1 = min(x0 + 1, 127);
    float wx = xs - (float)x0, omwx = 1.f - wx;

    float tC = s[x0] * omwx + s[x1] * wx;      // row g0 x-interp
    float best = -3.0e38f;
    int bidx = 0x7fffffff;

    #pragma unroll 4
    for (int lg = 0; lg < 32; ++lg) {
        const int gg = g0 + lg;
        const int y1l = min(gg + 1, 127) - g0;
        float c = s[y1l * 128 + x0];
        float d = s[y1l * 128 + x1];
        float tD = c * omwx + d * wx;
        float4 t4 = tab[gg];
        float diff = tD - tC;
        if (t4.z >= 0.f) {                     // group has output rows
            bool hi = diff > 0.f;
            float w   = hi ? t4.y : t4.x;
            float oyf = hi ? t4.w : t4.z;
            float v = fmaf(w, diff, tC);
            if (v > best) { best = v; bidx = (__float_as_int(oyf) << 9) + ox; }
        }
        tC = tD;
    }

    rv[tid] = best; ri[tid] = bidx;
    __syncthreads();
    for (int sft = 256; sft; sft >>= 1) {
        if (tid < sft) {
            float v2 = rv[tid + sft]; int i2 = ri[tid + sft];
            if (v2 > rv[tid] || (v2 == rv[tid] && i2 < ri[tid])) {
                rv[tid] = v2; ri[tid] = i2;
            }
        }
        __syncthreads();
    }

    if (tid == 0) {
        unsigned int u = __float_as_uint(rv[0]);
        u = (u & 0x80000000u) ? ~u : (u | 0x80000000u);
        unsigned long long key =
            ((unsigned long long)u << 32) | (0xFFFFFFFFu - (unsigned int)ri[0]);
        atomicMax(&g_best[m], key);
        __threadfence();
        s_ticket = atomicAdd(&g_count[m], 1u);
    }
    __syncthreads();

    // last block for this map runs the cascades
    if (s_ticket == 3u && tid < 32) {
        __threadfence();
        unsigned long long key;
        if (tid == 0) key = atomicAdd(&g_best[m], 0ULL);
        unsigned int lo = __shfl_sync(0xffffffffu, (unsigned int)(key & 0xFFFFFFFFull), 0);
        int idx = (int)(0xFFFFFFFFu - lo);
        float cx = (float)(idx & 511);
        float cy = (float)(idx >> 9);
        const float* imb = img + (size_t)(m / NP) * IMH * IMW;

        for (int casc = 0; casc < 3; ++casc) {
            int wi = (int)rintf(cx * 0.25f); wi = max(0, min(wi, 127));
            int hi = (int)rintf(cy * 0.25f); hi = max(0, min(hi, 127));
            float p0 = 0.f, p1 = 0.f;
            for (int t = tid; t < 49; t += 32) {
                int kh = t / 7, kw = t - kh * 7;
                int iy = hi * 4 - 3 + kh;
                int ix = wi * 4 - 3 + kw;
                float v = 0.f;
                if (iy >= 0 && iy < IMH && ix >= 0 && ix < IMW)
                    v = imb[iy * IMW + ix] - 0.5f;
                p0 += v * c_params[OFF_CW + (casc * 2 + 0) * 49 + t];
                p1 += v * c_params[OFF_CW + (casc * 2 + 1) * 49 + t];
            }
            #pragma unroll
            for (int sft = 16; sft; sft >>= 1) {
                p0 += __shfl_down_sync(0xffffffffu, p0, sft);
                p1 += __shfl_down_sync(0xffffffffu, p1, sft);
            }
            p0 = __shfl_sync(0xffffffffu, p0, 0);
            p1 = __shfl_sync(0xffffffffu, p1, 0);
            cx = cx + p0 + c_params[OFF_CB + casc * 2 + 0];
            cy = cy + p1 + c_params[OFF_CB + casc * 2 + 1];
        }
        if (tid == 0) { out[m * 2 + 0] = cx; out[m * 2 + 1] = cy; }
    }
}

// ---------------------------------------------------------------------------
extern "C" void kernel_launch(void* const* d_in, const int* in_sizes, int n_in,
                              void* d_out, int out_size) {
    const float* img = (const float*)d_in[0];
    const float* bw  = (const float*)d_in[1];
    const float* bb  = (const float*)d_in[2];
    const float* fcw = (const float*)d_in[3];
    const float* fcb = (const float*)d_in[4];
    const float* hw  = (const float*)d_in[5];
    const float* hb  = (const float*)d_in[6];
    float* out = (float*)d_out;

    prep_kernel<<<17, 256>>>(bw, bb, fcw, fcb, hw, hb);

    void* src = nullptr;
    cudaGetSymbolAddress(&src, g_params_dev);
    cudaMemcpyToSymbolAsync(c_params, src, NPARAMS * sizeof(float), 0,
                            cudaMemcpyDeviceToDevice, 0);

    dim3 gconv(4, 8, BATCH);
    conv_kernel<<<gconv, 256>>>(img);

    dim3 gam(4, NMAPS);
    argmax_cascade_kernel<<<gam, 512>>>(img, out);
}

// round 6
// speedup vs baseline: 1.1812x; 1.1812x over previous
#include <cuda_runtime.h>
#include <math.h>

#define BATCH 8
#define IMH 512
#define IMW 512
#define NP 11
#define FH 128
#define FW 128
#define NMAPS (BATCH * NP)

// packed derived parameters
// [0,539)    sw   : 11 score filters, 7x7 each          (sw[k*49+tap])
// [539,550)  sbias: 11 score biases
// [550,844)  cw   : 3 cascades x 2 dims x 49 taps       (cw[(i*2+j)*49+tap])
// [844,850)  cb   : 3 cascades x 2 dims
#define OFF_SW    0
#define OFF_SBIAS 539
#define OFF_CW    550
#define OFF_CB    844
#define NPARAMS   850

__device__    float g_params_dev[NPARAMS];
__constant__  float c_params[NPARAMS];

__device__ float g_scores[NMAPS * FH * FW];
__device__ unsigned long long g_best[NMAPS];
__device__ unsigned int       g_count[NMAPS];

// ---------------------------------------------------------------------------
// Kernel 1: fold weights. Block = one row r of the 17x(49+1) output matrix
// (11 fc rows + 6 head rows; 49 taps + 1 bias column). 512 threads.
// Two 128-channel halves:
//   Stage A: w_eff[c][p] = sum_i bw[c,i,p] -> smem (coalesced lanes over p,
//            ~12 unrolled iterations -> high MLP)
//   Stage B: thread (q,p), t=q*50+p: partial += coef[c]*we[c][p] over 16
//            channels (p contiguous in warp -> conflict-free LDS); scalar
//            register partial carried across halves.
// Final: thread p sums the 8 q-partials in fixed order (deterministic).
// Block 16 also resets the argmax combine state.
// ---------------------------------------------------------------------------
__global__ void prep_kernel(const float* __restrict__ bw,
                            const float* __restrict__ bb,
                            const float* __restrict__ fcw,
                            const float* __restrict__ fcb,
                            const float* __restrict__ hw,
                            const float* __restrict__ hb) {
    __shared__ float we[128 * 49];            // 25088 B
    __shared__ float cf[128];
    __shared__ float bbs[128];
    __shared__ float part[400];

    const int r = blockIdx.x;                 // 0..16
    const int t = threadIdx.x;                // 0..511

    if (r == 16 && t < NMAPS) { g_best[t] = 0ULL; g_count[t] = 0u; }

    const int ij = r - 11;                    // valid when r >= 11
    const int q = t / 50;                     // 0..7 (q<8 active in stage B)
    const int p = t - q * 50;                 // 0..49

    float acc = 0.f;

    for (int h = 0; h < 2; ++h) {
        __syncthreads();
        // Stage A: w_eff for channels [h*128, h*128+128)
        #pragma unroll 4
        for (int idx = t; idx < 128 * 49; idx += 512) {
            int c = idx / 49, pp = idx - c * 49;
            const float* base = bw + (h * 128 + c) * 147 + pp;
            we[idx] = base[0] + base[49] + base[98];
        }
        if (t < 128) {
            int c = h * 128 + t;
            cf[t]  = (r < 11) ? fcw[r * 256 + c]
                              : hw[((ij >> 1) * 256 + c) * 2 + (ij & 1)];
            bbs[t] = bb[c];
        }
        __syncthreads();

        // Stage B
        if (q < 8) {
            const int c0 = q * 16;
            if (p < 49) {
                #pragma unroll
                for (int s = 0; s < 16; ++s)
                    acc += cf[c0 + s] * we[(c0 + s) * 49 + p];
            } else {
                #pragma unroll
                for (int s = 0; s < 16; ++s)
                    acc += cf[c0 + s] * bbs[c0 + s];
            }
        }
    }

    __syncthreads();
    if (q < 8) part[q * 50 + p] = acc;
    __syncthreads();

    if (t < 50) {
        float tot = 0.f;
        #pragma unroll
        for (int qq = 0; qq < 8; ++qq) tot += part[qq * 50 + t];
        int slot; float base = 0.f;
        if (r < 11) {
            if (t < 49) slot = OFF_SW + r * 49 + t;
            else      { slot = OFF_SBIAS + r; base = fcb[r]; }
        } else {
            if (t < 49) slot = OFF_CW + ij * 49 + t;
            else      { slot = OFF_CB + ij; base = hb[ij]; }
        }
        g_params_dev[slot] = base + tot;
    }
}

// ---------------------------------------------------------------------------
// Kernel 2: 11-channel 7x7 stride-4 pad-3 conv of normalized image -> scores.
// Block = batch x (16 x 32) output tile; input tile in smem; weights from
// __constant__ (uniform across block -> const-bank FFMA operands).
// ---------------------------------------------------------------------------
__global__ void conv_kernel(const float* __restrict__ img) {
    __shared__ float tile[70 * 134];
    const int tx = blockIdx.x;
    const int ty = blockIdx.y;
    const int b  = blockIdx.z;
    const int tid = threadIdx.x;              // 256

    const float* imb = img + (size_t)b * IMH * IMW;
    const int ir0 = ty * 64 - 3;
    const int ic0 = tx * 128 - 3;

    for (int i = tid; i < 70 * 134; i += 256) {
        int r = i / 134, c = i - r * 134;
        int gr = ir0 + r, gc = ic0 + c;
        float v = 0.f;
        if (gr >= 0 && gr < IMH && gc >= 0 && gc < IMW)
            v = imb[gr * IMW + gc] - 0.5f;
        tile[i] = v;
    }
    __syncthreads();

    #pragma unroll
    for (int it = 0; it < 2; ++it) {
        int pos = tid + it * 256;
        int oyl = pos >> 5, oxl = pos & 31;
        float acc[NP];
        #pragma unroll
        for (int k = 0; k < NP; ++k) acc[k] = c_params[OFF_SBIAS + k];
        #pragma unroll
        for (int kh = 0; kh < 7; ++kh) {
            #pragma unroll
            for (int kw = 0; kw < 7; ++kw) {
                float v = tile[(oyl * 4 + kh) * 134 + oxl * 4 + kw];
                #pragma unroll
                for (int k = 0; k < NP; ++k)
                    acc[k] += v * c_params[OFF_SW + k * 49 + kh * 7 + kw];
            }
        }
        int oy = ty * 16 + oyl, ox = tx * 32 + oxl;
        #pragma unroll
        for (int k = 0; k < NP; ++k)
            g_scores[((b * NP + k) * FH + oy) * FW + ox] = acc[k];
    }
}

// ---------------------------------------------------------------------------
// Kernel 3: argmax over bilinear-upsampled field + cascades, split 4 blocks
// per map. Per cell-row group (same y0) the field is linear in wy -> max at
// endpoint rows. Rolling x-interp; per-map combine via atomicMax on
// (sortable value << 32 | ~idx) key (first-occurrence tie-break). Last block
// to finish a map runs the 3 cascade refinements (warp 0).
// ---------------------------------------------------------------------------
__global__ void argmax_cascade_kernel(const float* __restrict__ img,
                                      float* __restrict__ out) {
    __shared__ float  s[33 * 128];
    __shared__ float4 tab[128];
    __shared__ float  rv[512];
    __shared__ int    ri[512];
    __shared__ unsigned int s_ticket;

    const int sp  = blockIdx.x;                // 0..3
    const int m   = blockIdx.y;                // 0..87
    const int tid = threadIdx.x;               // 512
    const float STEP = 127.0f / 511.0f;
    const int g0 = sp * 32;
    const int nrows = (sp < 3) ? 33 : 32;
    const float* smap = g_scores + (size_t)m * FH * FW;

    {
        const float4* src = (const float4*)(smap + g0 * 128);
        float4* dst = (float4*)s;
        const int n4 = nrows * 32;
        for (int i = tid; i < n4; i += 512) dst[i] = src[i];
    }
    if (tid < 128) tab[tid].z = -1.0f;
    __syncthreads();

    {
        const int oy = tid;
        float ys = (float)oy * STEP;
        int y0 = (int)ys;
        float wy = ys - (float)y0;
        int y0m = (oy > 0)   ? (int)((float)(oy - 1) * STEP) : -1;
        int y0p = (oy < 511) ? (int)((float)(oy + 1) * STEP) : 128;
        if (y0m != y0) { tab[y0].x = wy; tab[y0].z = __int_as_float(oy); }
        if (y0p != y0) { tab[y0].y = wy; tab[y0].w = __int_as_float(oy); }
    }
    __syncthreads();

    const int ox = tid;
    float xs = (float)ox * STEP;
    int x0 = (int)xs;
    int x1 = min(x0 + 1, 127);
    float wx = xs - (float)x0, omwx = 1.f - wx;

    float tC = s[x0] * omwx + s[x1] * wx;
    float best = -3.0e38f;
    int bidx = 0x7fffffff;

    #pragma unroll 4
    for (int lg = 0; lg < 32; ++lg) {
        const int gg = g0 + lg;
        const int y1l = min(gg + 1, 127) - g0;
        float c = s[y1l * 128 + x0];
        float d = s[y1l * 128 + x1];
        float tD = c * omwx + d * wx;
        float4 t4 = tab[gg];
        float diff = tD - tC;
        if (t4.z >= 0.f) {
            bool hi = diff > 0.f;
            float w   = hi ? t4.y : t4.x;
            float oyf = hi ? t4.w : t4.z;
            float v = fmaf(w, diff, tC);
            if (v > best) { best = v; bidx = (__float_as_int(oyf) << 9) + ox; }
        }
        tC = tD;
    }

    rv[tid] = best; ri[tid] = bidx;
    __syncthreads();
    for (int sft = 256; sft; sft >>= 1) {
        if (tid < sft) {
            float v2 = rv[tid + sft]; int i2 = ri[tid + sft];
            if (v2 > rv[tid] || (v2 == rv[tid] && i2 < ri[tid])) {
                rv[tid] = v2; ri[tid] = i2;
            }
        }
        __syncthreads();
    }

    if (tid == 0) {
        unsigned int u = __float_as_uint(rv[0]);
        u = (u & 0x80000000u) ? ~u : (u | 0x80000000u);
        unsigned long long key =
            ((unsigned long long)u << 32) | (0xFFFFFFFFu - (unsigned int)ri[0]);
        atomicMax(&g_best[m], key);
        __threadfence();
        s_ticket = atomicAdd(&g_count[m], 1u);
    }
    __syncthreads();

    if (s_ticket == 3u && tid < 32) {
        __threadfence();
        unsigned long long key;
        if (tid == 0) key = atomicAdd(&g_best[m], 0ULL);
        unsigned int lo = __shfl_sync(0xffffffffu, (unsigned int)(key & 0xFFFFFFFFull), 0);
        int idx = (int)(0xFFFFFFFFu - lo);
        float cx = (float)(idx & 511);
        float cy = (float)(idx >> 9);
        const float* imb = img + (size_t)(m / NP) * IMH * IMW;

        for (int casc = 0; casc < 3; ++casc) {
            int wi = (int)rintf(cx * 0.25f); wi = max(0, min(wi, 127));
            int hi = (int)rintf(cy * 0.25f); hi = max(0, min(hi, 127));
            float p0 = 0.f, p1 = 0.f;
            for (int t = tid; t < 49; t += 32) {
                int kh = t / 7, kw = t - kh * 7;
                int iy = hi * 4 - 3 + kh;
                int ix = wi * 4 - 3 + kw;
                float v = 0.f;
                if (iy >= 0 && iy < IMH && ix >= 0 && ix < IMW)
                    v = imb[iy * IMW + ix] - 0.5f;
                p0 += v * c_params[OFF_CW + (casc * 2 + 0) * 49 + t];
                p1 += v * c_params[OFF_CW + (casc * 2 + 1) * 49 + t];
            }
            #pragma unroll
            for (int sft = 16; sft; sft >>= 1) {
                p0 += __shfl_down_sync(0xffffffffu, p0, sft);
                p1 += __shfl_down_sync(0xffffffffu, p1, sft);
            }
            p0 = __shfl_sync(0xffffffffu, p0, 0);
            p1 = __shfl_sync(0xffffffffu, p1, 0);
            cx = cx + p0 + c_params[OFF_CB + casc * 2 + 0];
            cy = cy + p1 + c_params[OFF_CB + casc * 2 + 1];
        }
        if (tid == 0) { out[m * 2 + 0] = cx; out[m * 2 + 1] = cy; }
    }
}

// ---------------------------------------------------------------------------
extern "C" void kernel_launch(void* const* d_in, const int* in_sizes, int n_in,
                              void* d_out, int out_size) {
    const float* img = (const float*)d_in[0];
    const float* bw  = (const float*)d_in[1];
    const float* bb  = (const float*)d_in[2];
    const float* fcw = (const float*)d_in[3];
    const float* fcb = (const float*)d_in[4];
    const float* hw  = (const float*)d_in[5];
    const float* hb  = (const float*)d_in[6];
    float* out = (float*)d_out;

    prep_kernel<<<17, 512>>>(bw, bb, fcw, fcb, hw, hb);

    void* src = nullptr;
    cudaGetSymbolAddress(&src, g_params_dev);
    cudaMemcpyToSymbolAsync(c_params, src, NPARAMS * sizeof(float), 0,
                            cudaMemcpyDeviceToDevice, 0);

    dim3 gconv(4, 8, BATCH);
    conv_kernel<<<gconv, 256>>>(img);

    dim3 gam(4, NMAPS);
    argmax_cascade_kernel<<<gam, 512>>>(img, out);
}

// round 7
// speedup vs baseline: 1.3361x; 1.1311x over previous
#include <cuda_runtime.h>
#include <math.h>

#define BATCH 8
#define IMH 512
#define IMW 512
#define NP 11
#define FH 128
#define FW 128
#define NMAPS (BATCH * NP)

// packed derived parameters
// [0,539)    sw   : 11 score filters, 7x7 each          (sw[k*49+tap])
// [539,550)  sbias: 11 score biases
// [550,844)  cw   : 3 cascades x 2 dims x 49 taps       (cw[(i*2+j)*49+tap])
// [844,850)  cb   : 3 cascades x 2 dims
#define OFF_SW    0
#define OFF_SBIAS 539
#define OFF_CW    550
#define OFF_CB    844
#define NPARAMS   850

__device__    float g_params_dev[NPARAMS];
__constant__  float c_params[NPARAMS];

__device__ float g_weff_T[49 * 256];          // w_eff transposed [p][c]
__device__ float g_scores[NMAPS * FH * FW];
__device__ unsigned long long g_best[NMAPS];
__device__ unsigned int       g_count[NMAPS];

// ---------------------------------------------------------------------------
// Kernel 1a: w_eff[c,p] = bw[c,0,p]+bw[c,1,p]+bw[c,2,p], stored transposed
// [p][c] so the fold kernel reads it coalesced. 12544 threads, 3 coalesced
// LDGs each. Block 0 also resets the argmax combine state.
// ---------------------------------------------------------------------------
__global__ void weff_kernel(const float* __restrict__ bw) {
    const int idx = blockIdx.x * 1024 + threadIdx.x;
    if (blockIdx.x == 0 && threadIdx.x < NMAPS) {
        g_best[threadIdx.x] = 0ULL;
        g_count[threadIdx.x] = 0u;
    }
    if (idx < 256 * 49) {
        const int c = idx / 49, p = idx - c * 49;
        const float* base = bw + c * 147 + p;
        g_weff_T[p * 256 + c] = base[0] + base[49] + base[98];
    }
}

// ---------------------------------------------------------------------------
// Kernel 1b: fold — one warp per output o in [0,850). Lanes stride channels;
// weff_T reads are lane-contiguous (coalesced, L2-hot). Shuffle reduce
// (fixed order -> deterministic), lane 0 stores.
// ---------------------------------------------------------------------------
__global__ void fold_kernel(const float* __restrict__ bb,
                            const float* __restrict__ fcw,
                            const float* __restrict__ fcb,
                            const float* __restrict__ hw,
                            const float* __restrict__ hb) {
    const int o = (blockIdx.x * blockDim.x + threadIdx.x) >> 5;
    const int l = threadIdx.x & 31;
    if (o >= 850) return;

    float acc = 0.f;
    if (o < 833) {
        const int grp = o / 49, p = o - grp * 49;   // warp-uniform
        const float* wt = g_weff_T + p * 256;
        if (grp < 11) {
            #pragma unroll
            for (int s = 0; s < 8; ++s) {
                int c = l + 32 * s;
                acc += fcw[grp * 256 + c] * wt[c];
            }
        } else {
            const int ij = grp - 11, i = ij >> 1, j = ij & 1;
            #pragma unroll
            for (int s = 0; s < 8; ++s) {
                int c = l + 32 * s;
                acc += hw[(i * 256 + c) * 2 + j] * wt[c];
            }
        }
    } else if (o < 844) {
        const int k = o - 833;
        #pragma unroll
        for (int s = 0; s < 8; ++s) {
            int c = l + 32 * s;
            acc += fcw[k * 256 + c] * bb[c];
        }
    } else {
        const int ij = o - 844, i = ij >> 1, j = ij & 1;
        #pragma unroll
        for (int s = 0; s < 8; ++s) {
            int c = l + 32 * s;
            acc += hw[(i * 256 + c) * 2 + j] * bb[c];
        }
    }

    #pragma unroll
    for (int sft = 16; sft; sft >>= 1)
        acc += __shfl_down_sync(0xffffffffu, acc, sft);

    if (l == 0) {
        int slot; float base = 0.f;
        if (o < 539)       slot = OFF_SW + o;
        else if (o < 833)  slot = OFF_CW + (o - 539);
        else if (o < 844) { slot = OFF_SBIAS + (o - 833); base = fcb[o - 833]; }
        else              { slot = OFF_CB + (o - 844);    base = hb[o - 844]; }
        g_params_dev[slot] = base + acc;
    }
}

// ---------------------------------------------------------------------------
// Kernel 2: 11-channel 7x7 stride-4 pad-3 conv of normalized image -> scores.
// Block = batch x (16 x 32) output tile; input tile in smem; weights from
// __constant__.
// ---------------------------------------------------------------------------
__global__ void conv_kernel(const float* __restrict__ img) {
    __shared__ float tile[70 * 134];
    const int tx = blockIdx.x;
    const int ty = blockIdx.y;
    const int b  = blockIdx.z;
    const int tid = threadIdx.x;              // 256

    const float* imb = img + (size_t)b * IMH * IMW;
    const int ir0 = ty * 64 - 3;
    const int ic0 = tx * 128 - 3;

    for (int i = tid; i < 70 * 134; i += 256) {
        int r = i / 134, c = i - r * 134;
        int gr = ir0 + r, gc = ic0 + c;
        float v = 0.f;
        if (gr >= 0 && gr < IMH && gc >= 0 && gc < IMW)
            v = imb[gr * IMW + gc] - 0.5f;
        tile[i] = v;
    }
    __syncthreads();

    #pragma unroll
    for (int it = 0; it < 2; ++it) {
        int pos = tid + it * 256;
        int oyl = pos >> 5, oxl = pos & 31;
        float acc[NP];
        #pragma unroll
        for (int k = 0; k < NP; ++k) acc[k] = c_params[OFF_SBIAS + k];
        #pragma unroll
        for (int kh = 0; kh < 7; ++kh) {
            #pragma unroll
            for (int kw = 0; kw < 7; ++kw) {
                float v = tile[(oyl * 4 + kh) * 134 + oxl * 4 + kw];
                #pragma unroll
                for (int k = 0; k < NP; ++k)
                    acc[k] += v * c_params[OFF_SW + k * 49 + kh * 7 + kw];
            }
        }
        int oy = ty * 16 + oyl, ox = tx * 32 + oxl;
        #pragma unroll
        for (int k = 0; k < NP; ++k)
            g_scores[((b * NP + k) * FH + oy) * FW + ox] = acc[k];
    }
}

// ---------------------------------------------------------------------------
// Kernel 3: argmax over bilinear-upsampled field + cascades, split 4 blocks
// per map. Per cell-row group (same y0) the field is linear in wy -> max at
// endpoint rows. Rolling x-interp; per-map combine via atomicMax on
// (sortable value << 32 | ~idx) key (first-occurrence tie-break). Last block
// to finish a map runs the 3 cascade refinements (warp 0).
// ---------------------------------------------------------------------------
__global__ void argmax_cascade_kernel(const float* __restrict__ img,
                                      float* __restrict__ out) {
    __shared__ float  s[33 * 128];
    __shared__ float4 tab[128];
    __shared__ float  rv[512];
    __shared__ int    ri[512];
    __shared__ unsigned int s_ticket;

    const int sp  = blockIdx.x;                // 0..3
    const int m   = blockIdx.y;                // 0..87
    const int tid = threadIdx.x;               // 512
    const float STEP = 127.0f / 511.0f;
    const int g0 = sp * 32;
    const int nrows = (sp < 3) ? 33 : 32;
    const float* smap = g_scores + (size_t)m * FH * FW;

    {
        const float4* src = (const float4*)(smap + g0 * 128);
        float4* dst = (float4*)s;
        const int n4 = nrows * 32;
        for (int i = tid; i < n4; i += 512) dst[i] = src[i];
    }
    if (tid < 128) tab[tid].z = -1.0f;
    __syncthreads();

    {
        const int oy = tid;
        float ys = (float)oy * STEP;
        int y0 = (int)ys;
        float wy = ys - (float)y0;
        int y0m = (oy > 0)   ? (int)((float)(oy - 1) * STEP) : -1;
        int y0p = (oy < 511) ? (int)((float)(oy + 1) * STEP) : 128;
        if (y0m != y0) { tab[y0].x = wy; tab[y0].z = __int_as_float(oy); }
        if (y0p != y0) { tab[y0].y = wy; tab[y0].w = __int_as_float(oy); }
    }
    __syncthreads();

    const int ox = tid;
    float xs = (float)ox * STEP;
    int x0 = (int)xs;
    int x1 = min(x0 + 1, 127);
    float wx = xs - (float)x0, omwx = 1.f - wx;

    float tC = s[x0] * omwx + s[x1] * wx;
    float best = -3.0e38f;
    int bidx = 0x7fffffff;

    #pragma unroll 4
    for (int lg = 0; lg < 32; ++lg) {
        const int gg = g0 + lg;
        const int y1l = min(gg + 1, 127) - g0;
        float c = s[y1l * 128 + x0];
        float d = s[y1l * 128 + x1];
        float tD = c * omwx + d * wx;
        float4 t4 = tab[gg];
        float diff = tD - tC;
        if (t4.z >= 0.f) {
            bool hi = diff > 0.f;
            float w   = hi ? t4.y : t4.x;
            float oyf = hi ? t4.w : t4.z;
            float v = fmaf(w, diff, tC);
            if (v > best) { best = v; bidx = (__float_as_int(oyf) << 9) + ox; }
        }
        tC = tD;
    }

    rv[tid] = best; ri[tid] = bidx;
    __syncthreads();
    for (int sft = 256; sft; sft >>= 1) {
        if (tid < sft) {
            float v2 = rv[tid + sft]; int i2 = ri[tid + sft];
            if (v2 > rv[tid] || (v2 == rv[tid] && i2 < ri[tid])) {
                rv[tid] = v2; ri[tid] = i2;
            }
        }
        __syncthreads();
    }

    if (tid == 0) {
        unsigned int u = __float_as_uint(rv[0]);
        u = (u & 0x80000000u) ? ~u : (u | 0x80000000u);
        unsigned long long key =
            ((unsigned long long)u << 32) | (0xFFFFFFFFu - (unsigned int)ri[0]);
        atomicMax(&g_best[m], key);
        __threadfence();
        s_ticket = atomicAdd(&g_count[m], 1u);
    }
    __syncthreads();

    if (s_ticket == 3u && tid < 32) {
        __threadfence();
        unsigned long long key;
        if (tid == 0) key = atomicAdd(&g_best[m], 0ULL);
        unsigned int lo = __shfl_sync(0xffffffffu, (unsigned int)(key & 0xFFFFFFFFull), 0);
        int idx = (int)(0xFFFFFFFFu - lo);
        float cx = (float)(idx & 511);
        float cy = (float)(idx >> 9);
        const float* imb = img + (size_t)(m / NP) * IMH * IMW;

        for (int casc = 0; casc < 3; ++casc) {
            int wi = (int)rintf(cx * 0.25f); wi = max(0, min(wi, 127));
            int hi = (int)rintf(cy * 0.25f); hi = max(0, min(hi, 127));
            float p0 = 0.f, p1 = 0.f;
            for (int t = tid; t < 49; t += 32) {
                int kh = t / 7, kw = t - kh * 7;
                int iy = hi * 4 - 3 + kh;
                int ix = wi * 4 - 3 + kw;
                float v = 0.f;
                if (iy >= 0 && iy < IMH && ix >= 0 && ix < IMW)
                    v = imb[iy * IMW + ix] - 0.5f;
                p0 += v * c_params[OFF_CW + (casc * 2 + 0) * 49 + t];
                p1 += v * c_params[OFF_CW + (casc * 2 + 1) * 49 + t];
            }
            #pragma unroll
            for (int sft = 16; sft; sft >>= 1) {
                p0 += __shfl_down_sync(0xffffffffu, p0, sft);
                p1 += __shfl_down_sync(0xffffffffu, p1, sft);
            }
            p0 = __shfl_sync(0xffffffffu, p0, 0);
            p1 = __shfl_sync(0xffffffffu, p1, 0);
            cx = cx + p0 + c_params[OFF_CB + casc * 2 + 0];
            cy = cy + p1 + c_params[OFF_CB + casc * 2 + 1];
        }
        if (tid == 0) { out[m * 2 + 0] = cx; out[m * 2 + 1] = cy; }
    }
}

// ---------------------------------------------------------------------------
extern "C" void kernel_launch(void* const* d_in, const int* in_sizes, int n_in,
                              void* d_out, int out_size) {
    const float* img = (const float*)d_in[0];
    const float* bw  = (const float*)d_in[1];
    const float* bb  = (const float*)d_in[2];
    const float* fcw = (const float*)d_in[3];
    const float* fcb = (const float*)d_in[4];
    const float* hw  = (const float*)d_in[5];
    const float* hb  = (const float*)d_in[6];
    float* out = (float*)d_out;

    weff_kernel<<<13, 1024>>>(bw);
    fold_kernel<<<107, 256>>>(bb, fcw, fcb, hw, hb);

    void* src = nullptr;
    cudaGetSymbolAddress(&src, g_params_dev);
    cudaMemcpyToSymbolAsync(c_params, src, NPARAMS * sizeof(float), 0,
                            cudaMemcpyDeviceToDevice, 0);

    dim3 gconv(4, 8, BATCH);
    conv_kernel<<<gconv, 256>>>(img);

    dim3 gam(4, NMAPS);
    argmax_cascade_kernel<<<gam, 512>>>(img, out);
}

// round 8
// speedup vs baseline: 1.4205x; 1.0632x over previous
#include <cuda_runtime.h>
#include <math.h>

#define BATCH 8
#define IMH 512
#define IMW 512
#define NP 11
#define FH 128
#define FW 128
#define NMAPS (BATCH * NP)

// packed derived parameters
// [0,539)    sw   : 11 score filters, 7x7 each          (sw[k*49+tap])
// [539,550)  sbias: 11 score biases
// [550,844)  cw   : 3 cascades x 2 dims x 49 taps       (cw[(i*2+j)*49+tap])
// [844,850)  cb   : 3 cascades x 2 dims
#define OFF_SW    0
#define OFF_SBIAS 539
#define OFF_CW    550
#define OFF_CB    844
#define NPARAMS   850

__device__    float g_params_dev[NPARAMS];
__constant__  float c_params[NPARAMS];

__device__ float g_weff_T[49 * 256];          // w_eff transposed [p][c]
__device__ unsigned long long g_best[NMAPS];
__device__ unsigned int       g_count[BATCH];

// ---------------------------------------------------------------------------
// Kernel 1a: w_eff[c,p] = bw[c,0,p]+bw[c,1,p]+bw[c,2,p], stored transposed
// [p][c]. Block 0 also resets the argmax combine state.
// ---------------------------------------------------------------------------
__global__ void weff_kernel(const float* __restrict__ bw) {
    const int idx = blockIdx.x * 1024 + threadIdx.x;
    if (blockIdx.x == 0) {
        if (threadIdx.x < NMAPS) g_best[threadIdx.x] = 0ULL;
        if (threadIdx.x < BATCH) g_count[threadIdx.x] = 0u;
    }
    if (idx < 256 * 49) {
        const int c = idx / 49, p = idx - c * 49;
        const float* base = bw + c * 147 + p;
        g_weff_T[p * 256 + c] = base[0] + base[49] + base[98];
    }
}

// ---------------------------------------------------------------------------
// Kernel 1b: fold — one warp per output o in [0,850). Lanes stride channels;
// weff_T reads lane-contiguous (coalesced, L2-hot). Shuffle reduce.
// ---------------------------------------------------------------------------
__global__ void fold_kernel(const float* __restrict__ bb,
                            const float* __restrict__ fcw,
                            const float* __restrict__ fcb,
                            const float* __restrict__ hw,
                            const float* __restrict__ hb) {
    const int o = (blockIdx.x * blockDim.x + threadIdx.x) >> 5;
    const int l = threadIdx.x & 31;
    if (o >= 850) return;

    float acc = 0.f;
    if (o < 833) {
        const int grp = o / 49, p = o - grp * 49;   // warp-uniform
        const float* wt = g_weff_T + p * 256;
        if (grp < 11) {
            #pragma unroll
            for (int s = 0; s < 8; ++s) {
                int c = l + 32 * s;
                acc += fcw[grp * 256 + c] * wt[c];
            }
        } else {
            const int ij = grp - 11, i = ij >> 1, j = ij & 1;
            #pragma unroll
            for (int s = 0; s < 8; ++s) {
                int c = l + 32 * s;
                acc += hw[(i * 256 + c) * 2 + j] * wt[c];
            }
        }
    } else if (o < 844) {
        const int k = o - 833;
        #pragma unroll
        for (int s = 0; s < 8; ++s) {
            int c = l + 32 * s;
            acc += fcw[k * 256 + c] * bb[c];
        }
    } else {
        const int ij = o - 844, i = ij >> 1, j = ij & 1;
        #pragma unroll
        for (int s = 0; s < 8; ++s) {
            int c = l + 32 * s;
            acc += hw[(i * 256 + c) * 2 + j] * bb[c];
        }
    }

    #pragma unroll
    for (int sft = 16; sft; sft >>= 1)
        acc += __shfl_down_sync(0xffffffffu, acc, sft);

    if (l == 0) {
        int slot; float base = 0.f;
        if (o < 539)       slot = OFF_SW + o;
        else if (o < 833)  slot = OFF_CW + (o - 539);
        else if (o < 844) { slot = OFF_SBIAS + (o - 833); base = fcb[o - 833]; }
        else              { slot = OFF_CB + (o - 844);    base = hb[o - 844]; }
        g_params_dev[slot] = base + acc;
    }
}

// ---------------------------------------------------------------------------
// Kernel 2 (fused): conv tile -> smem scores -> cell-corner argmax scan ->
// per-map atomicMax combine -> last block per batch runs cascades.
//
// Block = (tx, ty, b): 16x32 cell tile of batch image b; 352 threads
// (= 11 warps; warp k scans map k, lane = cell column, 16 rolling cell rows).
// Conv computes a 17x33 score halo tile (cells need +1 row/col corners).
// Per cell, bilinear max over contained output samples is at a corner:
// y-interp at each y-endpoint row, then x-endpoint chosen by slope sign.
// ---------------------------------------------------------------------------
__global__ void conv_scan_kernel(const float* __restrict__ img,
                                 float* __restrict__ out) {
    __shared__ float  sbuf[74 * 138];          // input tile, then scores
    __shared__ float4 tab[128];                // per-group {wlo, whi, olo, ohi}
    __shared__ unsigned int s_ticket;

    const int tx = blockIdx.x;                 // 0..3
    const int ty = blockIdx.y;                 // 0..7
    const int b  = blockIdx.z;                 // 0..7
    const int tid  = threadIdx.x;              // 0..351
    const int lane = tid & 31;
    const int wid  = tid >> 5;                 // 0..10
    const int gy0 = ty * 16, gx0 = tx * 32;
    const float STEP = 127.0f / 511.0f;

    const float* imb = img + (size_t)b * IMH * IMW;
    const int ir0 = ty * 64 - 3;
    const int ic0 = tx * 128 - 3;

    // 1. stage input tile (74 x 138, zero-padded)
    for (int i = tid; i < 74 * 138; i += 352) {
        int r = i / 138, c = i - r * 138;
        int gr = ir0 + r, gc = ic0 + c;
        float v = 0.f;
        if (gr >= 0 && gr < IMH && gc >= 0 && gc < IMW)
            v = imb[gr * IMW + gc] - 0.5f;
        sbuf[i] = v;
    }
    __syncthreads();

    // 2. conv: 561 positions (17 x 33), 2 per thread, accumulators in regs
    float acc[2][NP];
    #pragma unroll
    for (int it = 0; it < 2; ++it) {
        const int pos = tid + it * 352;
        #pragma unroll
        for (int k = 0; k < NP; ++k) acc[it][k] = c_params[OFF_SBIAS + k];
        if (pos < 561) {
            const int r = pos / 33, cl = pos - r * 33;
            const float* tp = sbuf + (r * 4) * 138 + cl * 4;
            #pragma unroll
            for (int kh = 0; kh < 7; ++kh) {
                #pragma unroll
                for (int kw = 0; kw < 7; ++kw) {
                    float v = tp[kh * 138 + kw];
                    #pragma unroll
                    for (int k = 0; k < NP; ++k)
                        acc[it][k] += v * c_params[OFF_SW + k * 49 + kh * 7 + kw];
                }
            }
        }
    }
    __syncthreads();                            // all tile reads done

    // 3. overlay scores into sbuf: s[k*561 + r*33 + c]
    #pragma unroll
    for (int it = 0; it < 2; ++it) {
        const int pos = tid + it * 352;
        if (pos < 561) {
            #pragma unroll
            for (int k = 0; k < NP; ++k) sbuf[k * 561 + pos] = acc[it][k];
        }
    }

    // 4. per-group endpoint table (all 128 groups; same for x and y)
    for (int oy = tid; oy < 512; oy += 352) {
        float ys = (float)oy * STEP;
        int y0 = (int)ys;
        float wy = ys - (float)y0;
        int y0m = (oy > 0)   ? (int)((float)(oy - 1) * STEP) : -1;
        int y0p = (oy < 511) ? (int)((float)(oy + 1) * STEP) : 128;
        if (y0m != y0) { tab[y0].x = wy; tab[y0].z = __int_as_float(oy); }
        if (y0p != y0) { tab[y0].y = wy; tab[y0].w = __int_as_float(oy); }
    }
    __syncthreads();

    // 5. scan: warp wid handles map k = wid; lane = cell column
    {
        const int k = wid;
        const int gx = gx0 + lane;
        const int c1l = min(gx + 1, 127) - gx0;
        const float* s = sbuf + k * 561;
        const float4 tx4 = tab[gx];

        float a  = s[lane];
        float bq = s[c1l];
        float best = -3.0e38f;
        int bidx = 0x7fffffff;

        #pragma unroll 4
        for (int r = 0; r < 16; ++r) {
            const int gy = gy0 + r;
            const int y1l = min(gy + 1, 127) - gy0;
            const float cc = s[y1l * 33 + lane];
            const float dd = s[y1l * 33 + c1l];
            const float4 ty4 = tab[gy];
            const float ca = cc - a, db = dd - bq;
            {   // y-lo endpoint row
                float rl = fmaf(ty4.x, ca, a);
                float rr = fmaf(ty4.x, db, bq);
                float dx = rr - rl;
                bool hx = dx > 0.f;
                float w  = hx ? tx4.y : tx4.x;
                int  oxs = __float_as_int(hx ? tx4.w : tx4.z);
                float v = fmaf(w, dx, rl);
                int idx = (__float_as_int(ty4.z) << 9) + oxs;
                if (v > best) { best = v; bidx = idx; }
            }
            {   // y-hi endpoint row
                float rl = fmaf(ty4.y, ca, a);
                float rr = fmaf(ty4.y, db, bq);
                float dx = rr - rl;
                bool hx = dx > 0.f;
                float w  = hx ? tx4.y : tx4.x;
                int  oxs = __float_as_int(hx ? tx4.w : tx4.z);
                float v = fmaf(w, dx, rl);
                int idx = (__float_as_int(ty4.w) << 9) + oxs;
                if (v > best) { best = v; bidx = idx; }
            }
            a = cc; bq = dd;
        }

        #pragma unroll
        for (int sft = 16; sft; sft >>= 1) {
            float v2 = __shfl_down_sync(0xffffffffu, best, sft);
            int   i2 = __shfl_down_sync(0xffffffffu, bidx, sft);
            if (v2 > best || (v2 == best && i2 < bidx)) { best = v2; bidx = i2; }
        }
        if (lane == 0) {
            unsigned int u = __float_as_uint(best);
            u = (u & 0x80000000u) ? ~u : (u | 0x80000000u);
            unsigned long long key =
                ((unsigned long long)u << 32) | (0xFFFFFFFFu - (unsigned int)bidx);
            atomicMax(&g_best[b * NP + k], key);
        }
    }

    __syncthreads();
    if (tid == 0) {
        __threadfence();
        s_ticket = atomicAdd(&g_count[b], 1u);
    }
    __syncthreads();

    // 6. last block of this batch: cascades, warp k -> point k
    if (s_ticket == 31u) {
        __threadfence();
        const int k = wid;
        unsigned long long key = 0ULL;
        if (lane == 0) key = atomicAdd(&g_best[b * NP + k], 0ULL);
        unsigned int lo =
            __shfl_sync(0xffffffffu, (unsigned int)(key & 0xFFFFFFFFull), 0);
        int idx = (int)(0xFFFFFFFFu - lo);
        float cx = (float)(idx & 511);
        float cy = (float)(idx >> 9);

        for (int casc = 0; casc < 3; ++casc) {
            int wi = (int)rintf(cx * 0.25f); wi = max(0, min(wi, 127));
            int hi = (int)rintf(cy * 0.25f); hi = max(0, min(hi, 127));
            float p0 = 0.f, p1 = 0.f;
            for (int t = lane; t < 49; t += 32) {
                int kh = t / 7, kw = t - kh * 7;
                int iy = hi * 4 - 3 + kh;
                int ix = wi * 4 - 3 + kw;
                float v = 0.f;
                if (iy >= 0 && iy < IMH && ix >= 0 && ix < IMW)
                    v = imb[iy * IMW + ix] - 0.5f;
                p0 += v * c_params[OFF_CW + (casc * 2 + 0) * 49 + t];
                p1 += v * c_params[OFF_CW + (casc * 2 + 1) * 49 + t];
            }
            #pragma unroll
            for (int sft = 16; sft; sft >>= 1) {
                p0 += __shfl_down_sync(0xffffffffu, p0, sft);
                p1 += __shfl_down_sync(0xffffffffu, p1, sft);
            }
            p0 = __shfl_sync(0xffffffffu, p0, 0);
            p1 = __shfl_sync(0xffffffffu, p1, 0);
            cx = cx + p0 + c_params[OFF_CB + casc * 2 + 0];
            cy = cy + p1 + c_params[OFF_CB + casc * 2 + 1];
        }
        if (lane == 0) {
            out[(b * NP + k) * 2 + 0] = cx;
            out[(b * NP + k) * 2 + 1] = cy;
        }
    }
}

// ---------------------------------------------------------------------------
extern "C" void kernel_launch(void* const* d_in, const int* in_sizes, int n_in,
                              void* d_out, int out_size) {
    const float* img = (const float*)d_in[0];
    const float* bw  = (const float*)d_in[1];
    const float* bb  = (const float*)d_in[2];
    const float* fcw = (const float*)d_in[3];
    const float* fcb = (const float*)d_in[4];
    const float* hw  = (const float*)d_in[5];
    const float* hb  = (const float*)d_in[6];
    float* out = (float*)d_out;

    weff_kernel<<<13, 1024>>>(bw);
    fold_kernel<<<107, 256>>>(bb, fcw, fcb, hw, hb);

    void* src = nullptr;
    cudaGetSymbolAddress(&src, g_params_dev);
    cudaMemcpyToSymbolAsync(c_params, src, NPARAMS * sizeof(float), 0,
                            cudaMemcpyDeviceToDevice, 0);

    dim3 g(4, 8, BATCH);
    conv_scan_kernel<<<g, 352>>>(img, out);
}

// round 9
// speedup vs baseline: 1.5234x; 1.0724x over previous
#include <cuda_runtime.h>
#include <math.h>

#define BATCH 8
#define IMH 512
#define IMW 512
#define NP 11
#define FH 128
#define FW 128
#define NMAPS (BATCH * NP)

// packed derived parameters (pair-interleaved conv weights for FFMA2)
// [0,588)    sw2  : 49 taps x 6 channel-pairs x 2  (slot = tap*12 + k, k<11;
//                   slot tap*12+11 is a zero hole)
// [588,600)  sb2  : 6 bias pairs (slot 588+k, k<11; 599 = zero hole)
// [600,894)  cw   : 3 cascades x 2 dims x 49 taps
// [894,900)  cb   : 3 cascades x 2 dims
#define OFF_SW2   0
#define OFF_SB2   588
#define OFF_CW    600
#define OFF_CB    894
#define NPARAMS   900

__device__   __align__(16) float g_params_dev[NPARAMS];
__constant__ __align__(16) float c_params[NPARAMS];

__device__ unsigned long long g_best[NMAPS];
__device__ unsigned int       g_count[BATCH];

// ---------------------------------------------------------------------------
// Kernel 1: merged fold — one warp per output o in [0,850). Lanes stride
// channels; w_eff computed on the fly from bw (strided loads; first-node
// cold cost dominates anyway). Warp 850 zeros the pair-layout holes.
// Block 0 resets the argmax combine state.
// ---------------------------------------------------------------------------
__global__ void prep_kernel(const float* __restrict__ bw,
                            const float* __restrict__ bb,
                            const float* __restrict__ fcw,
                            const float* __restrict__ fcb,
                            const float* __restrict__ hw,
                            const float* __restrict__ hb) {
    const int o = (blockIdx.x * blockDim.x + threadIdx.x) >> 5;
    const int l = threadIdx.x & 31;

    if (blockIdx.x == 0) {
        if (threadIdx.x < NMAPS) g_best[threadIdx.x] = 0ULL;
        if (threadIdx.x < BATCH) g_count[threadIdx.x] = 0u;
    }
    if (o > 850) return;

    if (o == 850) {                           // zero holes in pair layout
        if (l < 49) g_params_dev[OFF_SW2 + l * 12 + 11] = 0.f;
        int l2 = l + 32;
        if (l2 < 49) g_params_dev[OFF_SW2 + l2 * 12 + 11] = 0.f;
        if (l == 0)  g_params_dev[OFF_SB2 + 11] = 0.f;
        return;
    }

    float acc = 0.f;
    if (o < 833) {
        const int grp = o / 49, p = o - grp * 49;   // warp-uniform
        if (grp < 11) {
            #pragma unroll
            for (int s = 0; s < 8; ++s) {
                int c = l + 32 * s;
                const float* base = bw + c * 147 + p;
                float we = base[0] + base[49] + base[98];
                acc += fcw[grp * 256 + c] * we;
            }
        } else {
            const int ij = grp - 11, i = ij >> 1, j = ij & 1;
            #pragma unroll
            for (int s = 0; s < 8; ++s) {
                int c = l + 32 * s;
                const float* base = bw + c * 147 + p;
                float we = base[0] + base[49] + base[98];
                acc += hw[(i * 256 + c) * 2 + j] * we;
            }
        }
    } else if (o < 844) {
        const int k = o - 833;
        #pragma unroll
        for (int s = 0; s < 8; ++s) {
            int c = l + 32 * s;
            acc += fcw[k * 256 + c] * bb[c];
        }
    } else {
        const int ij = o - 844, i = ij >> 1, j = ij & 1;
        #pragma unroll
        for (int s = 0; s < 8; ++s) {
            int c = l + 32 * s;
            acc += hw[(i * 256 + c) * 2 + j] * bb[c];
        }
    }

    #pragma unroll
    for (int sft = 16; sft; sft >>= 1)
        acc += __shfl_down_sync(0xffffffffu, acc, sft);

    if (l == 0) {
        int slot; float base = 0.f;
        if (o < 539) {
            const int grp = o / 49, p = o - grp * 49;
            slot = OFF_SW2 + p * 12 + grp;          // pair-interleaved
        } else if (o < 833) {
            slot = OFF_CW + (o - 539);
        } else if (o < 844) {
            slot = OFF_SB2 + (o - 833); base = fcb[o - 833];
        } else {
            slot = OFF_CB + (o - 844);  base = hb[o - 844];
        }
        g_params_dev[slot] = base + acc;
    }
}

// ---------------------------------------------------------------------------
// Kernel 2 (fused): conv tile (FFMA2 packed channel pairs) -> smem scores ->
// cell-corner argmax scan -> per-map atomicMax combine -> last block per
// batch runs cascades. Block = (tx,ty,b) 16x32 cell tile, 352 threads
// (11 warps; warp k scans map k).
// ---------------------------------------------------------------------------
__global__ void conv_scan_kernel(const float* __restrict__ img,
                                 float* __restrict__ out) {
    __shared__ float  sbuf[74 * 138];          // input tile, then scores
    __shared__ float4 tab[128];
    __shared__ unsigned int s_ticket;

    const int tx = blockIdx.x;                 // 0..3
    const int ty = blockIdx.y;                 // 0..7
    const int b  = blockIdx.z;                 // 0..7
    const int tid  = threadIdx.x;              // 0..351
    const int lane = tid & 31;
    const int wid  = tid >> 5;                 // 0..10
    const int gy0 = ty * 16, gx0 = tx * 32;
    const float STEP = 127.0f / 511.0f;

    const float* imb = img + (size_t)b * IMH * IMW;
    const int ir0 = ty * 64 - 3;
    const int ic0 = tx * 128 - 3;

    // 1. stage input tile (74 x 138, zero-padded)
    for (int i = tid; i < 74 * 138; i += 352) {
        int r = i / 138, c = i - r * 138;
        int gr = ir0 + r, gc = ic0 + c;
        float v = 0.f;
        if (gr >= 0 && gr < IMH && gc >= 0 && gc < IMW)
            v = imb[gr * IMW + gc] - 0.5f;
        sbuf[i] = v;
    }
    __syncthreads();

    // 2. conv: 561 positions (17 x 33), 2/thread, packed f32x2 accumulators
    unsigned long long acc2[2][6];
    #pragma unroll
    for (int it = 0; it < 2; ++it) {
        const int pos = tid + it * 352;
        #pragma unroll
        for (int j = 0; j < 6; ++j)
            acc2[it][j] =
                *reinterpret_cast<const unsigned long long*>(&c_params[OFF_SB2 + 2 * j]);
        if (pos < 561) {
            const int r = pos / 33, cl = pos - r * 33;
            const float* tp = sbuf + (r * 4) * 138 + cl * 4;
            #pragma unroll
            for (int kh = 0; kh < 7; ++kh) {
                #pragma unroll
                for (int kw = 0; kw < 7; ++kw) {
                    float v = tp[kh * 138 + kw];
                    unsigned long long vv;
                    asm("mov.b64 %0, {%1, %1};" : "=l"(vv) : "f"(v));
                    const int tap = kh * 7 + kw;
                    #pragma unroll
                    for (int j = 0; j < 6; ++j) {
                        unsigned long long w =
                            *reinterpret_cast<const unsigned long long*>(
                                &c_params[OFF_SW2 + tap * 12 + 2 * j]);
                        asm("fma.rn.f32x2 %0, %1, %2, %3;"
                            : "=l"(acc2[it][j])
                            : "l"(w), "l"(vv), "l"(acc2[it][j]));
                    }
                }
            }
        }
    }
    __syncthreads();                            // all tile reads done

    // 3. overlay scores into sbuf: s[k*561 + r*33 + c]
    #pragma unroll
    for (int it = 0; it < 2; ++it) {
        const int pos = tid + it * 352;
        if (pos < 561) {
            #pragma unroll
            for (int j = 0; j < 6; ++j) {
                unsigned int lo = (unsigned int)(acc2[it][j] & 0xFFFFFFFFull);
                sbuf[(2 * j) * 561 + pos] = __uint_as_float(lo);
                if (j < 5) {
                    unsigned int hi = (unsigned int)(acc2[it][j] >> 32);
                    sbuf[(2 * j + 1) * 561 + pos] = __uint_as_float(hi);
                }
            }
        }
    }

    // 4. per-group endpoint table (same for x and y)
    for (int oy = tid; oy < 512; oy += 352) {
        float ys = (float)oy * STEP;
        int y0 = (int)ys;
        float wy = ys - (float)y0;
        int y0m = (oy > 0)   ? (int)((float)(oy - 1) * STEP) : -1;
        int y0p = (oy < 511) ? (int)((float)(oy + 1) * STEP) : 128;
        if (y0m != y0) { tab[y0].x = wy; tab[y0].z = __int_as_float(oy); }
        if (y0p != y0) { tab[y0].y = wy; tab[y0].w = __int_as_float(oy); }
    }
    __syncthreads();

    // 5. scan: warp wid handles map k = wid; lane = cell column
    {
        const int k = wid;
        const int gx = gx0 + lane;
        const int c1l = min(gx + 1, 127) - gx0;
        const float* s = sbuf + k * 561;
        const float4 tx4 = tab[gx];

        float a  = s[lane];
        float bq = s[c1l];
        float best = -3.0e38f;
        int bidx = 0x7fffffff;

        #pragma unroll 4
        for (int r = 0; r < 16; ++r) {
            const int gy = gy0 + r;
            const int y1l = min(gy + 1, 127) - gy0;
            const float cc = s[y1l * 33 + lane];
            const float dd = s[y1l * 33 + c1l];
            const float4 ty4 = tab[gy];
            const float ca = cc - a, db = dd - bq;
            {   // y-lo endpoint row
                float rl = fmaf(ty4.x, ca, a);
                float rr = fmaf(ty4.x, db, bq);
                float dx = rr - rl;
                bool hx = dx > 0.f;
                float w  = hx ? tx4.y : tx4.x;
                int  oxs = __float_as_int(hx ? tx4.w : tx4.z);
                float v = fmaf(w, dx, rl);
                int idx = (__float_as_int(ty4.z) << 9) + oxs;
                if (v > best) { best = v; bidx = idx; }
            }
            {   // y-hi endpoint row
                float rl = fmaf(ty4.y, ca, a);
                float rr = fmaf(ty4.y, db, bq);
                float dx = rr - rl;
                bool hx = dx > 0.f;
                float w  = hx ? tx4.y : tx4.x;
                int  oxs = __float_as_int(hx ? tx4.w : tx4.z);
                float v = fmaf(w, dx, rl);
                int idx = (__float_as_int(ty4.w) << 9) + oxs;
                if (v > best) { best = v; bidx = idx; }
            }
            a = cc; bq = dd;
        }

        #pragma unroll
        for (int sft = 16; sft; sft >>= 1) {
            float v2 = __shfl_down_sync(0xffffffffu, best, sft);
            int   i2 = __shfl_down_sync(0xffffffffu, bidx, sft);
            if (v2 > best || (v2 == best && i2 < bidx)) { best = v2; bidx = i2; }
        }
        if (lane == 0) {
            unsigned int u = __float_as_uint(best);
            u = (u & 0x80000000u) ? ~u : (u | 0x80000000u);
            unsigned long long key =
                ((unsigned long long)u << 32) | (0xFFFFFFFFu - (unsigned int)bidx);
            atomicMax(&g_best[b * NP + k], key);
        }
    }

    __syncthreads();
    if (tid == 0) {
        __threadfence();
        s_ticket = atomicAdd(&g_count[b], 1u);
    }
    __syncthreads();

    // 6. last block of this batch: cascades, warp k -> point k
    if (s_ticket == 31u) {
        __threadfence();
        const int k = wid;
        unsigned long long key = 0ULL;
        if (lane == 0) key = atomicAdd(&g_best[b * NP + k], 0ULL);
        unsigned int lo =
            __shfl_sync(0xffffffffu, (unsigned int)(key & 0xFFFFFFFFull), 0);
        int idx = (int)(0xFFFFFFFFu - lo);
        float cx = (float)(idx & 511);
        float cy = (float)(idx >> 9);

        for (int casc = 0; casc < 3; ++casc) {
            int wi = (int)rintf(cx * 0.25f); wi = max(0, min(wi, 127));
            int hi = (int)rintf(cy * 0.25f); hi = max(0, min(hi, 127));
            float p0 = 0.f, p1 = 0.f;
            for (int t = lane; t < 49; t += 32) {
                int kh = t / 7, kw = t - kh * 7;
                int iy = hi * 4 - 3 + kh;
                int ix = wi * 4 - 3 + kw;
                float v = 0.f;
                if (iy >= 0 && iy < IMH && ix >= 0 && ix < IMW)
                    v = imb[iy * IMW + ix] - 0.5f;
                p0 += v * c_params[OFF_CW + (casc * 2 + 0) * 49 + t];
                p1 += v * c_params[OFF_CW + (casc * 2 + 1) * 49 + t];
            }
            #pragma unroll
            for (int sft = 16; sft; sft >>= 1) {
                p0 += __shfl_down_sync(0xffffffffu, p0, sft);
                p1 += __shfl_down_sync(0xffffffffu, p1, sft);
            }
            p0 = __shfl_sync(0xffffffffu, p0, 0);
            p1 = __shfl_sync(0xffffffffu, p1, 0);
            cx = cx + p0 + c_params[OFF_CB + casc * 2 + 0];
            cy = cy + p1 + c_params[OFF_CB + casc * 2 + 1];
        }
        if (lane == 0) {
            out[(b * NP + k) * 2 + 0] = cx;
            out[(b * NP + k) * 2 + 1] = cy;
        }
    }
}

// ---------------------------------------------------------------------------
extern "C" void kernel_launch(void* const* d_in, const int* in_sizes, int n_in,
                              void* d_out, int out_size) {
    const float* img = (const float*)d_in[0];
    const float* bw  = (const float*)d_in[1];
    const float* bb  = (const float*)d_in[2];
    const float* fcw = (const float*)d_in[3];
    const float* fcb = (const float*)d_in[4];
    const float* hw  = (const float*)d_in[5];
    const float* hb  = (const float*)d_in[6];
    float* out = (float*)d_out;

    // 852 warps needed (850 outputs + hole-zero warp): 107 blocks x 256
    prep_kernel<<<107, 256>>>(bw, bb, fcw, fcb, hw, hb);

    void* src = nullptr;
    cudaGetSymbolAddress(&src, g_params_dev);
    cudaMemcpyToSymbolAsync(c_params, src, NPARAMS * sizeof(float), 0,
                            cudaMemcpyDeviceToDevice, 0);

    dim3 g(4, 8, BATCH);
    conv_scan_kernel<<<g, 352>>>(img, out);
}

// round 10
// speedup vs baseline: 1.8111x; 1.1889x over previous
#include <cuda_runtime.h>
#include <math.h>

#define BATCH 8
#define IMH 512
#define IMW 512
#define NP 11
#define NMAPS (BATCH * NP)

// packed derived parameters (pair-interleaved conv weights for FFMA2)
// [0,588)    sw2  : 49 taps x 6 channel-pairs x 2  (slot = tap*12 + k, k<11;
//                   slot tap*12+11 is a zero hole)
// [588,600)  sb2  : 6 bias pairs (slot 588+k, k<11; 599 = zero hole)
// [600,894)  cw   : 3 cascades x 2 dims x 49 taps
// [894,900)  cb   : 3 cascades x 2 dims
#define OFF_SW2   0
#define OFF_SB2   588
#define OFF_CW    600
#define OFF_CB    894
#define NPARAMS   900

__device__ __align__(16) float g_params_dev[NPARAMS];

__device__ unsigned long long g_best[NMAPS];
__device__ unsigned int       g_count[BATCH];

// ---------------------------------------------------------------------------
// Kernel 1: fold weights — one warp per output o in [0,850). Warp 850 zeros
// the pair-layout holes. Block 0 resets the argmax combine state.
// ---------------------------------------------------------------------------
__global__ void prep_kernel(const float* __restrict__ bw,
                            const float* __restrict__ bb,
                            const float* __restrict__ fcw,
                            const float* __restrict__ fcb,
                            const float* __restrict__ hw,
                            const float* __restrict__ hb) {
    const int o = (blockIdx.x * blockDim.x + threadIdx.x) >> 5;
    const int l = threadIdx.x & 31;

    if (blockIdx.x == 0) {
        if (threadIdx.x < NMAPS) g_best[threadIdx.x] = 0ULL;
        if (threadIdx.x < BATCH) g_count[threadIdx.x] = 0u;
    }
    if (o > 850) return;

    if (o == 850) {                           // zero holes in pair layout
        if (l < 49) g_params_dev[OFF_SW2 + l * 12 + 11] = 0.f;
        int l2 = l + 32;
        if (l2 < 49) g_params_dev[OFF_SW2 + l2 * 12 + 11] = 0.f;
        if (l == 0)  g_params_dev[OFF_SB2 + 11] = 0.f;
        return;
    }

    float acc = 0.f;
    if (o < 833) {
        const int grp = o / 49, p = o - grp * 49;   // warp-uniform
        if (grp < 11) {
            #pragma unroll
            for (int s = 0; s < 8; ++s) {
                int c = l + 32 * s;
                const float* base = bw + c * 147 + p;
                float we = base[0] + base[49] + base[98];
                acc += fcw[grp * 256 + c] * we;
            }
        } else {
            const int ij = grp - 11, i = ij >> 1, j = ij & 1;
            #pragma unroll
            for (int s = 0; s < 8; ++s) {
                int c = l + 32 * s;
                const float* base = bw + c * 147 + p;
                float we = base[0] + base[49] + base[98];
                acc += hw[(i * 256 + c) * 2 + j] * we;
            }
        }
    } else if (o < 844) {
        const int k = o - 833;
        #pragma unroll
        for (int s = 0; s < 8; ++s) {
            int c = l + 32 * s;
            acc += fcw[k * 256 + c] * bb[c];
        }
    } else {
        const int ij = o - 844, i = ij >> 1, j = ij & 1;
        #pragma unroll
        for (int s = 0; s < 8; ++s) {
            int c = l + 32 * s;
            acc += hw[(i * 256 + c) * 2 + j] * bb[c];
        }
    }

    #pragma unroll
    for (int sft = 16; sft; sft >>= 1)
        acc += __shfl_down_sync(0xffffffffu, acc, sft);

    if (l == 0) {
        int slot; float base = 0.f;
        if (o < 539) {
            const int grp = o / 49, p = o - grp * 49;
            slot = OFF_SW2 + p * 12 + grp;          // pair-interleaved
        } else if (o < 833) {
            slot = OFF_CW + (o - 539);
        } else if (o < 844) {
            slot = OFF_SB2 + (o - 833); base = fcb[o - 833];
        } else {
            slot = OFF_CB + (o - 844);  base = hb[o - 844];
        }
        g_params_dev[slot] = base + acc;
    }
}

// ---------------------------------------------------------------------------
// Kernel 2 (fused): stage params+tile -> conv (FFMA2, weights from smem,
// vectorized value loads, weight loads shared by 2 positions) -> smem scores
// -> cell-corner argmax scan -> per-map atomicMax -> last block per batch
// runs cascades. Block = (tx,ty,b) 16x32 cell tile, 352 threads (11 warps).
// Tile stride 140 so each kh-row of 7 values is LDS.128+LDS.64+LDS aligned.
// ---------------------------------------------------------------------------
__global__ void conv_scan_kernel(const float* __restrict__ img,
                                 float* __restrict__ out) {
    __shared__ __align__(16) float sbuf[74 * 140];  // input tile, then scores
    __shared__ __align__(16) float wsm[NPARAMS];    // folded params
    __shared__ float4 tab[128];
    __shared__ unsigned int s_ticket;

    const int tx = blockIdx.x;                 // 0..3
    const int ty = blockIdx.y;                 // 0..7
    const int b  = blockIdx.z;                 // 0..7
    const int tid  = threadIdx.x;              // 0..351
    const int lane = tid & 31;
    const int wid  = tid >> 5;                 // 0..10
    const int gy0 = ty * 16, gx0 = tx * 32;
    const float STEP = 127.0f / 511.0f;

    const float* imb = img + (size_t)b * IMH * IMW;
    const int ir0 = ty * 64 - 3;
    const int ic0 = tx * 128 - 3;

    // phase 0: params -> smem, tile -> smem, endpoint table
    for (int i = tid; i < NPARAMS; i += 352) wsm[i] = g_params_dev[i];

    const bool interior = (ir0 >= 0) && (ir0 + 74 <= IMH) &&
                          (ic0 >= 0) && (ic0 + 138 <= IMW);
    if (interior) {
        const float* src = imb + ir0 * IMW + ic0;
        for (int i = tid; i < 74 * 138; i += 352) {
            int r = i / 138, c = i - r * 138;
            sbuf[r * 140 + c] = src[r * IMW + c] - 0.5f;
        }
    } else {
        for (int i = tid; i < 74 * 138; i += 352) {
            int r = i / 138, c = i - r * 138;
            int gr = ir0 + r, gc = ic0 + c;
            float v = 0.f;
            if (gr >= 0 && gr < IMH && gc >= 0 && gc < IMW)
                v = imb[gr * IMW + gc] - 0.5f;
            sbuf[r * 140 + c] = v;
        }
    }
    for (int oy = tid; oy < 512; oy += 352) {
        float ys = (float)oy * STEP;
        int y0 = (int)ys;
        float wy = ys - (float)y0;
        int y0m = (oy > 0)   ? (int)((float)(oy - 1) * STEP) : -1;
        int y0p = (oy < 511) ? (int)((float)(oy + 1) * STEP) : 128;
        if (y0m != y0) { tab[y0].x = wy; tab[y0].z = __int_as_float(oy); }
        if (y0p != y0) { tab[y0].y = wy; tab[y0].w = __int_as_float(oy); }
    }
    __syncthreads();

    // phase 1: conv — positions pos0=tid, pos1=min(tid+352,560)
    const int pos0 = tid;
    const int pos1 = min(tid + 352, 560);
    const int r0 = pos0 / 33, c0 = pos0 - r0 * 33;
    const int r1 = pos1 / 33, c1 = pos1 - r1 * 33;
    const float* tp0 = sbuf + (r0 * 4) * 140 + c0 * 4;
    const float* tp1 = sbuf + (r1 * 4) * 140 + c1 * 4;

    unsigned long long acc2[2][6];
    #pragma unroll
    for (int j = 0; j < 6; ++j) {
        unsigned long long bias =
            *reinterpret_cast<const unsigned long long*>(&wsm[OFF_SB2 + 2 * j]);
        acc2[0][j] = bias;
        acc2[1][j] = bias;
    }

    #pragma unroll
    for (int kh = 0; kh < 7; ++kh) {
        const float* rp0 = tp0 + kh * 140;
        const float* rp1 = tp1 + kh * 140;
        float4 A0 = *reinterpret_cast<const float4*>(rp0);
        float2 B0 = *reinterpret_cast<const float2*>(rp0 + 4);
        float  C0 = rp0[6];
        float4 A1 = *reinterpret_cast<const float4*>(rp1);
        float2 B1 = *reinterpret_cast<const float2*>(rp1 + 4);
        float  C1 = rp1[6];
        float v0[7] = {A0.x, A0.y, A0.z, A0.w, B0.x, B0.y, C0};
        float v1[7] = {A1.x, A1.y, A1.z, A1.w, B1.x, B1.y, C1};
        #pragma unroll
        for (int kw = 0; kw < 7; ++kw) {
            const int tapo = (kh * 7 + kw) * 12;
            unsigned long long vv0, vv1;
            asm("mov.b64 %0, {%1, %1};" : "=l"(vv0) : "f"(v0[kw]));
            asm("mov.b64 %0, {%1, %1};" : "=l"(vv1) : "f"(v1[kw]));
            #pragma unroll
            for (int j = 0; j < 6; ++j) {
                unsigned long long w =
                    *reinterpret_cast<const unsigned long long*>(
                        &wsm[OFF_SW2 + tapo + 2 * j]);
                asm("fma.rn.f32x2 %0, %1, %2, %3;"
                    : "=l"(acc2[0][j]) : "l"(w), "l"(vv0), "l"(acc2[0][j]));
                asm("fma.rn.f32x2 %0, %1, %2, %3;"
                    : "=l"(acc2[1][j]) : "l"(w), "l"(vv1), "l"(acc2[1][j]));
            }
        }
    }
    __syncthreads();                            // all tile reads done

    // phase 2: overlay scores into sbuf: s[k*561 + pos]
    #pragma unroll
    for (int j = 0; j < 6; ++j) {
        unsigned int lo0 = (unsigned int)(acc2[0][j] & 0xFFFFFFFFull);
        sbuf[(2 * j) * 561 + pos0] = __uint_as_float(lo0);
        if (j < 5) {
            unsigned int hi0 = (unsigned int)(acc2[0][j] >> 32);
            sbuf[(2 * j + 1) * 561 + pos0] = __uint_as_float(hi0);
        }
    }
    if (tid < 209) {
        #pragma unroll
        for (int j = 0; j < 6; ++j) {
            unsigned int lo1 = (unsigned int)(acc2[1][j] & 0xFFFFFFFFull);
            sbuf[(2 * j) * 561 + pos1] = __uint_as_float(lo1);
            if (j < 5) {
                unsigned int hi1 = (unsigned int)(acc2[1][j] >> 32);
                sbuf[(2 * j + 1) * 561 + pos1] = __uint_as_float(hi1);
            }
        }
    }
    __syncthreads();

    // phase 3: scan — warp wid handles map k = wid; lane = cell column
    {
        const int k = wid;
        const int gx = gx0 + lane;
        const int c1l = min(gx + 1, 127) - gx0;
        const float* s = sbuf + k * 561;
        const float4 tx4 = tab[gx];

        float a  = s[lane];
        float bq = s[c1l];
        float best = -3.0e38f;
        int bidx = 0x7fffffff;

        #pragma unroll 4
        for (int r = 0; r < 16; ++r) {
            const int gy = gy0 + r;
            const int y1l = min(gy + 1, 127) - gy0;
            const float cc = s[y1l * 33 + lane];
            const float dd = s[y1l * 33 + c1l];
            const float4 ty4 = tab[gy];
            const float ca = cc - a, db = dd - bq;
            {   // y-lo endpoint row
                float rl = fmaf(ty4.x, ca, a);
                float rr = fmaf(ty4.x, db, bq);
                float dx = rr - rl;
                bool hx = dx > 0.f;
                float w  = hx ? tx4.y : tx4.x;
                int  oxs = __float_as_int(hx ? tx4.w : tx4.z);
                float v = fmaf(w, dx, rl);
                int idx = (__float_as_int(ty4.z) << 9) + oxs;
                if (v > best) { best = v; bidx = idx; }
            }
            {   // y-hi endpoint row
                float rl = fmaf(ty4.y, ca, a);
                float rr = fmaf(ty4.y, db, bq);
                float dx = rr - rl;
                bool hx = dx > 0.f;
                float w  = hx ? tx4.y : tx4.x;
                int  oxs = __float_as_int(hx ? tx4.w : tx4.z);
                float v = fmaf(w, dx, rl);
                int idx = (__float_as_int(ty4.w) << 9) + oxs;
                if (v > best) { best = v; bidx = idx; }
            }
            a = cc; bq = dd;
        }

        #pragma unroll
        for (int sft = 16; sft; sft >>= 1) {
            float v2 = __shfl_down_sync(0xffffffffu, best, sft);
            int   i2 = __shfl_down_sync(0xffffffffu, bidx, sft);
            if (v2 > best || (v2 == best && i2 < bidx)) { best = v2; bidx = i2; }
        }
        if (lane == 0) {
            unsigned int u = __float_as_uint(best);
            u = (u & 0x80000000u) ? ~u : (u | 0x80000000u);
            unsigned long long key =
                ((unsigned long long)u << 32) | (0xFFFFFFFFu - (unsigned int)bidx);
            atomicMax(&g_best[b * NP + k], key);
        }
    }

    __syncthreads();
    if (tid == 0) {
        __threadfence();
        s_ticket = atomicAdd(&g_count[b], 1u);
    }
    __syncthreads();

    // phase 4: last block of this batch: cascades, warp k -> point k
    if (s_ticket == 31u) {
        __threadfence();
        const int k = wid;
        unsigned long long key = 0ULL;
        if (lane == 0) key = atomicAdd(&g_best[b * NP + k], 0ULL);
        unsigned int lo =
            __shfl_sync(0xffffffffu, (unsigned int)(key & 0xFFFFFFFFull), 0);
        int idx = (int)(0xFFFFFFFFu - lo);
        float cx = (float)(idx & 511);
        float cy = (float)(idx >> 9);

        for (int casc = 0; casc < 3; ++casc) {
            int wi = (int)rintf(cx * 0.25f); wi = max(0, min(wi, 127));
            int hi = (int)rintf(cy * 0.25f); hi = max(0, min(hi, 127));
            float p0 = 0.f, p1 = 0.f;
            for (int t = lane; t < 49; t += 32) {
                int kh = t / 7, kw = t - kh * 7;
                int iy = hi * 4 - 3 + kh;
                int ix = wi * 4 - 3 + kw;
                float v = 0.f;
                if (iy >= 0 && iy < IMH && ix >= 0 && ix < IMW)
                    v = imb[iy * IMW + ix] - 0.5f;
                p0 += v * wsm[OFF_CW + (casc * 2 + 0) * 49 + t];
                p1 += v * wsm[OFF_CW + (casc * 2 + 1) * 49 + t];
            }
            #pragma unroll
            for (int sft = 16; sft; sft >>= 1) {
                p0 += __shfl_down_sync(0xffffffffu, p0, sft);
                p1 += __shfl_down_sync(0xffffffffu, p1, sft);
            }
            p0 = __shfl_sync(0xffffffffu, p0, 0);
            p1 = __shfl_sync(0xffffffffu, p1, 0);
            cx = cx + p0 + wsm[OFF_CB + casc * 2 + 0];
            cy = cy + p1 + wsm[OFF_CB + casc * 2 + 1];
        }
        if (lane == 0) {
            out[(b * NP + k) * 2 + 0] = cx;
            out[(b * NP + k) * 2 + 1] = cy;
        }
    }
}

// ---------------------------------------------------------------------------
extern "C" void kernel_launch(void* const* d_in, const int* in_sizes, int n_in,
                              void* d_out, int out_size) {
    const float* img = (const float*)d_in[0];
    const float* bw  = (const float*)d_in[1];
    const float* bb  = (const float*)d_in[2];
    const float* fcw = (const float*)d_in[3];
    const float* fcb = (const float*)d_in[4];
    const float* hw  = (const float*)d_in[5];
    const float* hb  = (const float*)d_in[6];
    float* out = (float*)d_out;

    prep_kernel<<<107, 256>>>(bw, bb, fcw, fcb, hw, hb);

    dim3 g(4, 8, BATCH);
    conv_scan_kernel<<<g, 352>>>(img, out);
}